// round 8
// baseline (speedup 1.0000x reference)
#include <cuda_runtime.h>
#include <cuda_bf16.h>
#include <math.h>

// ---------------------------------------------------------------------------
// GCN on B200 (sm_100a).
// R8: R7 (4-stage cp.async pipeline, BK=16) with the commit-group tail-race
//     fixed: empty commit_group keeps the wait_group ledger aligned.
// ---------------------------------------------------------------------------

#define NN 50000
#define NE 1600000
#define FIN 512
#define FHID 128
#define FOUT 64

__device__ int   g_is64;
__device__ float g_dinv[NN];
__device__ int   g_count[NN];
__device__ int   g_ptr[NN + 1];
__device__ int   g_cursor[NN];
__device__ int   g_srcs[NE];
__device__ __align__(256) __nv_bfloat16 g_xh[(size_t)NN * FIN];
__device__ __align__(256) __nv_bfloat16 g_xl[(size_t)NN * FIN];
__device__ __align__(256) __nv_bfloat16 g_w1h[FHID * FIN];  // [n][k]
__device__ __align__(256) __nv_bfloat16 g_w1l[FHID * FIN];
__device__ __align__(256) __nv_bfloat16 g_h1h[(size_t)NN * FHID];
__device__ __align__(256) __nv_bfloat16 g_h1l[(size_t)NN * FHID];
__device__ __align__(256) __nv_bfloat16 g_w2h[FOUT * FHID];  // [n][k]
__device__ __align__(256) __nv_bfloat16 g_w2l[FOUT * FHID];
__device__ __align__(256) float g_tmp1[(size_t)NN * FHID];  // dinv*(x@W1)
__device__ __align__(256) float g_tmp2[(size_t)NN * FOUT];  // dinv*(h1@W2)

__device__ __forceinline__ int edge_at(const void* p, long long idx) {
    return g_is64 ? (int)((const long long*)p)[idx] : ((const int*)p)[idx];
}

// zero degree counters + dtype detect (int64 => odd 32-bit words all zero)
__global__ void setup_kernel(const unsigned int* __restrict__ p) {
    int i = blockIdx.x * blockDim.x + threadIdx.x;
    if (i < NN) g_count[i] = 0;
    if (i == 0) {
        int all0 = 1;
        for (int j = 1; j < 256 && all0; j += 2)
            if (p[j] != 0u) all0 = 0;
        g_is64 = all0;
    }
}

__global__ void degree_kernel(const void* __restrict__ ei, int E) {
    int i = blockIdx.x * blockDim.x + threadIdx.x;
    if (i < E) atomicAdd(&g_count[edge_at(ei, (long long)E + i)], 1);
}

// ---- one fused conversion kernel (x, W1, W2 -> bf16 hi/lo; W transposed)
__global__ void convert_kernel(const float* __restrict__ x,
                               const float* __restrict__ W1,
                               const float* __restrict__ W2) {
    int bx = blockIdx.x;
    if (bx < 25000) {
        int i = bx * 256 + threadIdx.x;  // float4 index
        float4 v = *(const float4*)(x + (size_t)i * 4);
        __nv_bfloat16 hx = __float2bfloat16(v.x);
        __nv_bfloat16 hy = __float2bfloat16(v.y);
        __nv_bfloat16 hz = __float2bfloat16(v.z);
        __nv_bfloat16 hw = __float2bfloat16(v.w);
        *(__nv_bfloat162*)(g_xh + (size_t)i * 4) = __nv_bfloat162(hx, hy);
        *(__nv_bfloat162*)(g_xh + (size_t)i * 4 + 2) = __nv_bfloat162(hz, hw);
        *(__nv_bfloat162*)(g_xl + (size_t)i * 4) = __nv_bfloat162(
            __float2bfloat16(v.x - __bfloat162float(hx)),
            __float2bfloat16(v.y - __bfloat162float(hy)));
        *(__nv_bfloat162*)(g_xl + (size_t)i * 4 + 2) = __nv_bfloat162(
            __float2bfloat16(v.z - __bfloat162float(hz)),
            __float2bfloat16(v.w - __bfloat162float(hw)));
    } else if (bx < 25256) {
        int j = (bx - 25000) * 256 + threadIdx.x;  // [0, 65536)
        int n = j / FIN, k = j % FIN;
        float v = W1[(size_t)k * FHID + n];
        __nv_bfloat16 h = __float2bfloat16(v);
        g_w1h[j] = h;
        g_w1l[j] = __float2bfloat16(v - __bfloat162float(h));
    } else {
        int j = (bx - 25256) * 256 + threadIdx.x;  // [0, 8192)
        int n = j / FHID, k = j % FHID;
        float v = W2[(size_t)k * FOUT + n];
        __nv_bfloat16 h = __float2bfloat16(v);
        g_w2h[j] = h;
        g_w2l[j] = __float2bfloat16(v - __bfloat162float(h));
    }
}

// exclusive scan of g_count -> g_ptr/g_cursor; also emits dinv. 1 block.
__global__ void scan_kernel() {
    __shared__ int warpsums[32];
    __shared__ int s_carry;
    int tid = threadIdx.x, lane = tid & 31, wid = tid >> 5;
    if (tid == 0) s_carry = 0;
    __syncthreads();
    for (int base = 0; base < NN; base += 1024) {
        int i = base + tid;
        int v = (i < NN) ? g_count[i] : 0;
        if (i < NN) g_dinv[i] = rsqrtf((float)(v + 1));
        int x = v;
#pragma unroll
        for (int off = 1; off < 32; off <<= 1) {
            int y = __shfl_up_sync(0xffffffffu, x, off);
            if (lane >= off) x += y;
        }
        if (lane == 31) warpsums[wid] = x;
        __syncthreads();
        if (wid == 0) {
            int s = warpsums[lane];
#pragma unroll
            for (int off = 1; off < 32; off <<= 1) {
                int y = __shfl_up_sync(0xffffffffu, s, off);
                if (lane >= off) s += y;
            }
            warpsums[lane] = s;
        }
        __syncthreads();
        int woff = wid ? warpsums[wid - 1] : 0;
        int incl = x + woff + s_carry;
        if (i < NN) { g_ptr[i] = incl - v; g_cursor[i] = incl - v; }
        __syncthreads();
        if (tid == 1023) s_carry = incl;
        __syncthreads();
    }
    if (tid == 0) g_ptr[NN] = s_carry;
}

__global__ void build_kernel(const void* __restrict__ ei, int E) {
    int i = blockIdx.x * blockDim.x + threadIdx.x;
    if (i < E) {
        int s = edge_at(ei, i);
        int d = edge_at(ei, (long long)E + i);
        g_srcs[atomicAdd(&g_cursor[d], 1)] = s;
    }
}

// ---------------------------------------------------------------------------
// bf16 hi/lo split GEMM: C = dinv[row]*(A@B), A:[M][K] hi/lo, B:[N][K] hi/lo.
// 4-stage cp.async pipeline + ldmatrix + m16n8k16 (3 MMAs per frag pair).
// ---------------------------------------------------------------------------
#define MMA_BF16(d, a, b)                                                     \
    asm volatile(                                                             \
        "mma.sync.aligned.m16n8k16.row.col.f32.bf16.bf16.f32 "                \
        "{%0,%1,%2,%3},{%4,%5,%6,%7},{%8,%9},{%0,%1,%2,%3};"                  \
        : "+f"(d[0]), "+f"(d[1]), "+f"(d[2]), "+f"(d[3])                      \
        : "r"(a[0]), "r"(a[1]), "r"(a[2]), "r"(a[3]), "r"(b[0]), "r"(b[1]))

#define LDSM4(r0, r1, r2, r3, addr)                                           \
    asm volatile("ldmatrix.sync.aligned.m8n8.x4.shared.b16 {%0,%1,%2,%3},[%4];" \
                 : "=r"(r0), "=r"(r1), "=r"(r2), "=r"(r3) : "r"(addr))

__device__ __forceinline__ void cp16(void* s, const void* g, bool ok) {
    unsigned sa = (unsigned)__cvta_generic_to_shared(s);
    int sz = ok ? 16 : 0;
    asm volatile("cp.async.cg.shared.global [%0], [%1], 16, %2;"
                 :: "r"(sa), "l"(g), "r"(sz));
}

template <int BM, int BN, int WARPS_M, int WARPS_N, int K_, int GEMM_ID>
__global__ __launch_bounds__(256) void gemm_bf16(int M) {
    constexpr int BK = 16;
    constexpr int BKP = BK + 8;  // 24 bf16 = 48B rows: LDSM-conflict-free
    constexpr int WM = BM / WARPS_M;
    constexpr int WN = BN / WARPS_N;
    constexpr int MFRAG = WM / 16;
    constexpr int NFRAG = WN / 8;
    constexpr int KT = K_ / BK;
    constexpr int STAGE = (2 * BM + 2 * BN) * BKP;  // bf16 elems per stage

    extern __shared__ __nv_bfloat16 smem[];

    const __nv_bfloat16* Agh = (GEMM_ID == 1) ? g_xh : g_h1h;
    const __nv_bfloat16* Agl = (GEMM_ID == 1) ? g_xl : g_h1l;
    const __nv_bfloat16* Bgh = (GEMM_ID == 1) ? g_w1h : g_w2h;
    const __nv_bfloat16* Bgl = (GEMM_ID == 1) ? g_w1l : g_w2l;
    float* C = (GEMM_ID == 1) ? (float*)g_tmp1 : (float*)g_tmp2;
    constexpr int N_ = BN;  // one block column covers all of N

    const int tid = threadIdx.x;
    const int lane = tid & 31, warp = tid >> 5;
    const int g = lane >> 2, t = lane & 3;
    const int wm = warp / WARPS_N, wn = warp % WARPS_N;
    const int m0 = blockIdx.x * BM;
    const unsigned sbase = (unsigned)__cvta_generic_to_shared(smem);

    float acc[MFRAG][NFRAG][4] = {};

    auto load_stage = [&](int s, int k0) {
        __nv_bfloat16* sAh = smem + s * STAGE;
        __nv_bfloat16* sAl = sAh + BM * BKP;
        __nv_bfloat16* sBh = sAh + 2 * BM * BKP;
        __nv_bfloat16* sBl = sBh + BN * BKP;
#pragma unroll 2
        for (int i = tid; i < BM * (BK / 8); i += 256) {
            int r = i / (BK / 8), c = (i % (BK / 8)) * 8;
            bool ok = (m0 + r) < M;
            size_t go = (size_t)(m0 + r) * K_ + k0 + c;
            cp16(sAh + r * BKP + c, Agh + go, ok);
            cp16(sAl + r * BKP + c, Agl + go, ok);
        }
#pragma unroll 2
        for (int i = tid; i < BN * (BK / 8); i += 256) {
            int r = i / (BK / 8), c = (i % (BK / 8)) * 8;
            size_t go = (size_t)r * K_ + k0 + c;
            cp16(sBh + r * BKP + c, Bgh + go, true);
            cp16(sBl + r * BKP + c, Bgl + go, true);
        }
        asm volatile("cp.async.commit_group;");
    };

    // per-lane ldmatrix address offsets
    const int a_row = lane & 15, a_col = (lane >> 4) << 3;
    const int b_row = ((lane >> 4) << 3) + (lane & 7);
    const int b_col = ((lane >> 3) & 1) << 3;

    load_stage(0, 0);
    load_stage(1, BK);
    load_stage(2, 2 * BK);

#pragma unroll 1
    for (int kt = 0; kt < KT; kt++) {
        asm volatile("cp.async.wait_group 2;");
        __syncthreads();  // stage kt ready; buffer (kt+3)&3 freed by all warps
        if (kt + 3 < KT) {
            load_stage((kt + 3) & 3, (kt + 3) * BK);
        } else {
            // empty commit keeps exactly 3 groups pending at each wait, so
            // wait_group 2 always retires precisely stage kt's group.
            asm volatile("cp.async.commit_group;");
        }

        const int s = kt & 3;
        const unsigned uAh = sbase + (s * STAGE) * 2;
        const unsigned uAl = uAh + BM * BKP * 2;
        const unsigned uBh = sbase + (s * STAGE + 2 * BM * BKP) * 2;
        const unsigned uBl = uBh + BN * BKP * 2;

        unsigned ah[MFRAG][4], al[MFRAG][4], bh[NFRAG][2], bl[NFRAG][2];
        const unsigned aoff = ((wm * WM + a_row) * BKP + a_col) * 2;
#pragma unroll
        for (int i = 0; i < MFRAG; i++) {
            LDSM4(ah[i][0], ah[i][1], ah[i][2], ah[i][3],
                  uAh + aoff + i * 16 * BKP * 2);
            LDSM4(al[i][0], al[i][1], al[i][2], al[i][3],
                  uAl + aoff + i * 16 * BKP * 2);
        }
        const unsigned boff = ((wn * WN + b_row) * BKP + b_col) * 2;
#pragma unroll
        for (int jp = 0; jp < NFRAG / 2; jp++) {
            LDSM4(bh[2 * jp][0], bh[2 * jp][1], bh[2 * jp + 1][0],
                  bh[2 * jp + 1][1], uBh + boff + jp * 16 * BKP * 2);
            LDSM4(bl[2 * jp][0], bl[2 * jp][1], bl[2 * jp + 1][0],
                  bl[2 * jp + 1][1], uBl + boff + jp * 16 * BKP * 2);
        }
#pragma unroll
        for (int i = 0; i < MFRAG; i++)
#pragma unroll
            for (int j = 0; j < NFRAG; j++) {
                MMA_BF16(acc[i][j], al[i], bh[j]);
                MMA_BF16(acc[i][j], ah[i], bl[j]);
                MMA_BF16(acc[i][j], ah[i], bh[j]);
            }
        __syncthreads();
    }

    // epilogue: scale by dinv (GEMM1: from counts; GEMM2: from g_dinv)
#pragma unroll
    for (int i = 0; i < MFRAG; i++) {
        int r0 = m0 + wm * WM + i * 16 + g;
        int r1 = r0 + 8;
        float dv0 = 0.f, dv1 = 0.f;
        if (GEMM_ID == 1) {
            if (r0 < M) dv0 = rsqrtf((float)(g_count[r0] + 1));
            if (r1 < M) dv1 = rsqrtf((float)(g_count[r1] + 1));
        } else {
            if (r0 < M) dv0 = g_dinv[r0];
            if (r1 < M) dv1 = g_dinv[r1];
        }
#pragma unroll
        for (int j = 0; j < NFRAG; j++) {
            int c = wn * WN + j * 8 + t * 2;
            if (r0 < M) {
                float2 o = {dv0 * acc[i][j][0], dv0 * acc[i][j][1]};
                *(float2*)(C + (size_t)r0 * N_ + c) = o;
            }
            if (r1 < M) {
                float2 o = {dv1 * acc[i][j][2], dv1 * acc[i][j][3]};
                *(float2*)(C + (size_t)r1 * N_ + c) = o;
            }
        }
    }
}

// ---------------------------------------------------------------------------
// prop1: h1 = relu(dinv*(tmp1_self + sum tmp1[src]) + b1), emitted as bf16 h/l.
// ---------------------------------------------------------------------------
__global__ void prop1_kernel(const float* __restrict__ bias, int M) {
    int lane = threadIdx.x & 31, warp = threadIdx.x >> 5;
    int node = blockIdx.x * 8 + warp;
    if (node >= M) return;
    const float* hs = (const float*)g_tmp1;
    int beg = g_ptr[node], end = g_ptr[node + 1];
    float dv = g_dinv[node];

    float4 acc = *(const float4*)(hs + (size_t)node * FHID + lane * 4);
    for (int c = beg; c < end; c += 32) {
        int idx = c + lane;
        int s = (idx < end) ? g_srcs[idx] : 0;
        int n = min(32, end - c);
        for (int j = 0; j < n; j++) {
            int sj = __shfl_sync(0xffffffffu, s, j);
            float4 v = *(const float4*)(hs + (size_t)sj * FHID + lane * 4);
            acc.x += v.x; acc.y += v.y; acc.z += v.z; acc.w += v.w;
        }
    }
    float4 b4 = *(const float4*)(bias + lane * 4);
    float o[4];
    o[0] = fmaxf(dv * acc.x + b4.x, 0.f);
    o[1] = fmaxf(dv * acc.y + b4.y, 0.f);
    o[2] = fmaxf(dv * acc.z + b4.z, 0.f);
    o[3] = fmaxf(dv * acc.w + b4.w, 0.f);
    __nv_bfloat16 hh[4], ll[4];
#pragma unroll
    for (int q = 0; q < 4; q++) {
        hh[q] = __float2bfloat16(o[q]);
        ll[q] = __float2bfloat16(o[q] - __bfloat162float(hh[q]));
    }
    size_t base = (size_t)node * FHID + lane * 4;
    *(__nv_bfloat162*)(g_h1h + base) = __nv_bfloat162(hh[0], hh[1]);
    *(__nv_bfloat162*)(g_h1h + base + 2) = __nv_bfloat162(hh[2], hh[3]);
    *(__nv_bfloat162*)(g_h1l + base) = __nv_bfloat162(ll[0], ll[1]);
    *(__nv_bfloat162*)(g_h1l + base + 2) = __nv_bfloat162(ll[2], ll[3]);
}

// ---------------------------------------------------------------------------
// prop2 + final linear + log_softmax, fused.
// ---------------------------------------------------------------------------
__global__ void prop2_final_kernel(const float* __restrict__ b2,
                                   const float* __restrict__ Wl,
                                   const float* __restrict__ bl,
                                   float* __restrict__ out, int M) {
    __shared__ float sW[64 * 64];
    __shared__ float sb[64];
    int tid = threadIdx.x;
    for (int i = tid; i < 64 * 64; i += 256) sW[i] = Wl[i];
    if (tid < 64) sb[tid] = bl[tid];
    __syncthreads();

    int lane = tid & 31, warp = tid >> 5;
    int node = blockIdx.x * 8 + warp;
    if (node >= M) return;

    const float* hs = (const float*)g_tmp2;
    int beg = g_ptr[node], end = g_ptr[node + 1];
    float dv = g_dinv[node];

    float2 acc = *(const float2*)(hs + (size_t)node * FOUT + lane * 2);
    for (int c = beg; c < end; c += 32) {
        int idx = c + lane;
        int s = (idx < end) ? g_srcs[idx] : 0;
        int n = min(32, end - c);
        for (int j = 0; j < n; j++) {
            int sj = __shfl_sync(0xffffffffu, s, j);
            float2 v = *(const float2*)(hs + (size_t)sj * FOUT + lane * 2);
            acc.x += v.x; acc.y += v.y;
        }
    }
    float2 bb = *(const float2*)(b2 + lane * 2);
    float2 h2;
    h2.x = dv * acc.x + bb.x;
    h2.y = dv * acc.y + bb.y;

    float l0 = 0.f, l1 = 0.f;
#pragma unroll
    for (int q = 0; q < 32; q++) {
        float hx = __shfl_sync(0xffffffffu, h2.x, q);
        float hy = __shfl_sync(0xffffffffu, h2.y, q);
        l0 += hx * sW[(2 * q) * 64 + lane] + hy * sW[(2 * q + 1) * 64 + lane];
        l1 += hx * sW[(2 * q) * 64 + lane + 32] +
              hy * sW[(2 * q + 1) * 64 + lane + 32];
    }
    l0 += sb[lane];
    l1 += sb[lane + 32];

    float m = fmaxf(l0, l1);
#pragma unroll
    for (int off = 16; off; off >>= 1)
        m = fmaxf(m, __shfl_xor_sync(0xffffffffu, m, off));
    float s = expf(l0 - m) + expf(l1 - m);
#pragma unroll
    for (int off = 16; off; off >>= 1)
        s += __shfl_xor_sync(0xffffffffu, s, off);
    float lse = m + logf(s);

    out[(size_t)node * 64 + lane] = l0 - lse;
    out[(size_t)node * 64 + lane + 32] = l1 - lse;
}

// ---------------------------------------------------------------------------
extern "C" void kernel_launch(void* const* d_in, const int* in_sizes, int n_in,
                              void* d_out, int out_size) {
    const float* x  = (const float*)d_in[0];
    const void*  ei = d_in[1];
    const float* W1 = (const float*)d_in[2];
    const float* b1 = (const float*)d_in[3];
    const float* W2 = (const float*)d_in[4];
    const float* b2 = (const float*)d_in[5];
    const float* Wl = (const float*)d_in[6];
    const float* bl = (const float*)d_in[7];
    float* out = (float*)d_out;

    int M = in_sizes[0] / FIN;  // 50000
    int E = in_sizes[1] / 2;    // 1600000

    setup_kernel<<<(NN + 255) / 256, 256>>>((const unsigned int*)ei);  // #1
    degree_kernel<<<(E + 255) / 256, 256>>>(ei, E);                    // #2
    convert_kernel<<<25288, 256>>>(x, W1, W2);                         // #3

    // GEMM1: [50000,512]x[512,128]  (profiled slot #4)
    {
        constexpr int BM = 128, BN = 128;
        constexpr int SM = 4 * (2 * BM + 2 * BN) * 24 * 2;  // bytes
        auto k = gemm_bf16<BM, BN, 2, 4, FIN, 1>;
        cudaFuncSetAttribute(k, cudaFuncAttributeMaxDynamicSharedMemorySize, SM);
        k<<<(M + BM - 1) / BM, 256, SM>>>(M);                          // #4
    }
    scan_kernel<<<1, 1024>>>();                                        // #5
    build_kernel<<<(E + 255) / 256, 256>>>(ei, E);                     // #6
    prop1_kernel<<<(M + 7) / 8, 256>>>(b1, M);                         // #7
    // GEMM2: [50000,128]x[128,64]
    {
        constexpr int BM = 128, BN = 64;
        constexpr int SM = 4 * (2 * BM + 2 * BN) * 24 * 2;
        auto k = gemm_bf16<BM, BN, 4, 2, FHID, 2>;
        cudaFuncSetAttribute(k, cudaFuncAttributeMaxDynamicSharedMemorySize, SM);
        k<<<(M + BM - 1) / BM, 256, SM>>>(M);                          // #8
    }
    prop2_final_kernel<<<(M + 7) / 8, 256>>>(b2, Wl, bl, out, M);      // #9
}